// round 3
// baseline (speedup 1.0000x reference)
#include <cuda_runtime.h>
#include <math.h>

#define BB 2
#define SS 128
#define HH 256
#define CC 8
#define PAD 260        // main-kernel smem row stride (floats, multiple of 4)

// ---------------- scratch (device globals; no allocation allowed) ----------
__device__ float g_z[BB * SS * HH];            // 256 KB
__device__ float g_e[BB * CC * SS];            // 8 KB   [b][c][s]
__device__ float g_cumexp[BB * SS * CC];       // 8 KB   [b][s][c]
__device__ float g_cumm[BB * SS * CC * HH];    // 2 MB   [b][s][c][h]

// ---------------------------------------------------------------------------
// Kernel A: z[b,s,h] = relu(memory[b,s,:] . W_w[h,:] + W_b[h])
// grid 64 = (16 row-tiles of 16 rows) x (4 h-quarters of 64); 256 threads.
// Thread = (h-lane 64) x (row-group 4, 4 rows each). memory rows staged in
// smem and read warp-broadcast (conflict-free); Ww read per-thread from
// global via float4 (L2-resident, hidden by 4-row ILP).
// ---------------------------------------------------------------------------
__global__ void __launch_bounds__(256) kernelA(const float* __restrict__ memory,
                                               const float* __restrict__ Ww,
                                               const float* __restrict__ Wb)
{
    __shared__ float Msh[16 * HH];   // 16 KB

    int bid = blockIdx.x;
    int r0 = (bid >> 2) * 16;        // first global row (b*S+s)
    int h0 = (bid & 3) * 64;         // h quarter
    int tid = threadIdx.x;

    // stage 16 memory rows (coalesced float4)
    for (int t = tid; t < 16 * 64; t += 256) {
        int rr = t >> 6;
        int k4 = (t & 63) * 4;
        *(float4*)&Msh[rr * HH + k4] = *(const float4*)&memory[(r0 + rr) * HH + k4];
    }
    __syncthreads();

    int h  = h0 + (tid & 63);        // output column
    int rg = tid >> 6;               // row group 0..3 -> rows rg*4 .. rg*4+3
    float bias = Wb[h];
    float acc[4] = {bias, bias, bias, bias};

    const float4* wrow = (const float4*)&Ww[h * HH];
    const float4* m0 = (const float4*)&Msh[(rg * 4 + 0) * HH];
    const float4* m1 = (const float4*)&Msh[(rg * 4 + 1) * HH];
    const float4* m2 = (const float4*)&Msh[(rg * 4 + 2) * HH];
    const float4* m3 = (const float4*)&Msh[(rg * 4 + 3) * HH];
#pragma unroll 8
    for (int k4 = 0; k4 < HH / 4; k4++) {
        float4 w = wrow[k4];
        float4 a = m0[k4];           // broadcast within warp
        float4 b = m1[k4];
        float4 c = m2[k4];
        float4 d = m3[k4];
        acc[0] = fmaf(a.x, w.x, acc[0]); acc[0] = fmaf(a.y, w.y, acc[0]);
        acc[0] = fmaf(a.z, w.z, acc[0]); acc[0] = fmaf(a.w, w.w, acc[0]);
        acc[1] = fmaf(b.x, w.x, acc[1]); acc[1] = fmaf(b.y, w.y, acc[1]);
        acc[1] = fmaf(b.z, w.z, acc[1]); acc[1] = fmaf(b.w, w.w, acc[1]);
        acc[2] = fmaf(c.x, w.x, acc[2]); acc[2] = fmaf(c.y, w.y, acc[2]);
        acc[2] = fmaf(c.z, w.z, acc[2]); acc[2] = fmaf(c.w, w.w, acc[2]);
        acc[3] = fmaf(d.x, w.x, acc[3]); acc[3] = fmaf(d.y, w.y, acc[3]);
        acc[3] = fmaf(d.z, w.z, acc[3]); acc[3] = fmaf(d.w, w.w, acc[3]);
    }
#pragma unroll
    for (int r = 0; r < 4; r++)
        g_z[(r0 + rg * 4 + r) * HH + h] = fmaxf(acc[r], 0.0f);
}

// ---------------------------------------------------------------------------
// Kernel B1: per (b,c): score[s] = U_w[c,:].z[b,s,:]; softmax-exp; inclusive
// cumsum over s -> g_cumexp; also store e -> g_e.
// grid 16 = B*C, 128 threads (4 warps).
// ---------------------------------------------------------------------------
__global__ void __launch_bounds__(128) kernelB1(const float* __restrict__ Uw)
{
    __shared__ float Ush[HH];
    __shared__ float sc[SS];
    __shared__ float wred[4];
    __shared__ float wsum[4];

    int b = blockIdx.x >> 3;
    int c = blockIdx.x & 7;
    int tid = threadIdx.x;
    int lane = tid & 31, w = tid >> 5;

    if (tid < 64)
        *(float4*)&Ush[tid * 4] = *(const float4*)&Uw[c * HH + tid * 4];
    __syncthreads();

    // warp-cooperative dot products, coalesced z reads
    const float4* Ush4 = (const float4*)Ush;
    for (int it = 0; it < 32; it++) {
        int s = w + it * 4;
        const float4* zr = (const float4*)&g_z[(b * SS + s) * HH];
        float4 z0 = zr[lane * 2];
        float4 z1 = zr[lane * 2 + 1];
        float4 u0 = Ush4[lane * 2];
        float4 u1 = Ush4[lane * 2 + 1];
        float p = z0.x * u0.x + z0.y * u0.y + z0.z * u0.z + z0.w * u0.w
                + z1.x * u1.x + z1.y * u1.y + z1.z * u1.z + z1.w * u1.w;
#pragma unroll
        for (int o = 16; o > 0; o >>= 1)
            p += __shfl_xor_sync(0xffffffffu, p, o);
        if (lane == 0) sc[s] = p;
    }
    __syncthreads();

    // max reduce over 128 values
    float v = sc[tid];
    float m = v;
#pragma unroll
    for (int o = 16; o > 0; o >>= 1)
        m = fmaxf(m, __shfl_xor_sync(0xffffffffu, m, o));
    if (lane == 0) wred[w] = m;
    __syncthreads();
    float mx = fmaxf(fmaxf(wred[0], wred[1]), fmaxf(wred[2], wred[3]));

    float e = expf(v - mx);
    float x = e;
#pragma unroll
    for (int o = 1; o < 32; o <<= 1) {
        float t = __shfl_up_sync(0xffffffffu, x, o);
        if (lane >= o) x += t;
    }
    if (lane == 31) wsum[w] = x;
    __syncthreads();
    float pre = 0.0f;
    for (int ww = 0; ww < w; ww++) pre += wsum[ww];

    g_e[(b * CC + c) * SS + tid] = e;
    g_cumexp[(b * SS + tid) * CC + c] = x + pre;
}

// ---------------------------------------------------------------------------
// Kernel B2: g_cumm[b,s,c,h] = inclusive cumsum_s( memory[b,s,h] * e[b,c,s] )
// grid 16 = B x (8 h-chunks of 32); 256 threads = 8 c x 32 h.
// ---------------------------------------------------------------------------
__global__ void __launch_bounds__(256) kernelB2(const float* __restrict__ memory)
{
    __shared__ float esh[CC * SS];
    int b = blockIdx.x >> 3;
    int hc = blockIdx.x & 7;
    int tid = threadIdx.x;

    for (int t = tid; t < CC * SS; t += 256)
        esh[t] = g_e[b * CC * SS + t];
    __syncthreads();

    int c = tid >> 5;
    int h = hc * 32 + (tid & 31);
    const float* mp = memory + (size_t)b * SS * HH + h;
    float* op = g_cumm + ((size_t)(b * SS) * CC + c) * HH + h;
    const float* ep = &esh[c * SS];
    float acc = 0.0f;
#pragma unroll 4
    for (int s = 0; s < SS; s++) {
        acc = fmaf(mp[(size_t)s * HH], ep[s], acc);
        op[(size_t)s * (CC * HH)] = acc;
    }
}

// ---------------------------------------------------------------------------
// Main kernel:
//   out[b,i,j,c] = (sum_h relu(R[j,h]-P[i,h]) * V[c,h]) / denom + V_b[c]
//   P[i,:] = (gi==0 ? 0 : cumm[b,gi-1,c,:]);  R[j,:] = cumm[b,gj,c,:]
// grid 512 = b(2) x i-tile(8) x j-tile(8) x c-pair(4); 256 threads.
// warps: 2 local c x 4 h-quarters; lanes: 8 ilane x 4 jlane; tile 2i x 4j.
// ---------------------------------------------------------------------------
__global__ void __launch_bounds__(256, 2) kernelMain(const float* __restrict__ Vw,
                                                     const float* __restrict__ Vb,
                                                     float* __restrict__ out)
{
    extern __shared__ float sm[];
    float* Psh = sm;                   // 32 * PAD = 8320
    float* Rsh = sm + 8320;            // 8320
    float* Vsh = sm + 16640;           // 512
    float* red = sm + 17152;           // 4*512 = 2048   (total 19200 fl = 76800 B)

    int bid = blockIdx.x;
    int cpair = bid & 3;
    int jt = (bid >> 2) & 7;
    int it = (bid >> 5) & 7;
    int b = bid >> 8;
    int i0 = it * 16, j0 = jt * 16, cbase = cpair * 2;
    int tid = threadIdx.x;

    // stage V (2 c x 256 h)
    if (tid < 128)
        *(float4*)&Vsh[tid * 4] = *(const float4*)&Vw[cbase * HH + tid * 4];

    // stage P and R tiles: 32 rows each (2c x 16); per-quarter-warp constant
    // row -> STS.128 phases conflict-free; LDG.128 coalesced (8 lanes = 128B)
    {
        int rr = tid >> 3;             // 0..31
        int c4 = tid & 7;
        int cl = rr >> 4, ir = rr & 15;
        int gi = i0 + ir;
        int gj = j0 + ir;
        const float* srcR = &g_cumm[((size_t)(b * SS + gj) * CC + cbase + cl) * HH];
        const float* srcP = (gi == 0) ? (const float*)0
            : &g_cumm[((size_t)(b * SS + gi - 1) * CC + cbase + cl) * HH];
        float* dstR = &Rsh[rr * PAD];
        float* dstP = &Psh[rr * PAD];
#pragma unroll
        for (int k = 0; k < 8; k++) {
            int h = c4 * 4 + k * 32;
            *(float4*)&dstR[h] = *(const float4*)&srcR[h];
            float4 pv = srcP ? *(const float4*)&srcP[h] : make_float4(0.f, 0.f, 0.f, 0.f);
            *(float4*)&dstP[h] = pv;
        }
    }
    __syncthreads();

    int lane = tid & 31, w = tid >> 5;
    int cl = w & 1;                    // local c
    int hq = w >> 1;                   // h quarter 0..3
    int ilane = lane >> 2;             // 0..7
    int jlane = lane & 3;              // 0..3

    const float* Pb = &Psh[(cl * 16) * PAD];
    const float* Rb = &Rsh[(cl * 16) * PAD];
    const float* Vp = &Vsh[cl * HH];

    float acc[2][4];
#pragma unroll
    for (int ii = 0; ii < 2; ii++)
#pragma unroll
        for (int jj = 0; jj < 4; jj++) acc[ii][jj] = 0.0f;

    int hbase = hq * 64;
#pragma unroll 4
    for (int hh = 0; hh < 64; hh += 4) {
        int h = hbase + hh;
        float4 v  = *(const float4*)&Vp[h];
        float4 p0 = *(const float4*)&Pb[ilane * PAD + h];
        float4 p1 = *(const float4*)&Pb[(ilane + 8) * PAD + h];
#pragma unroll
        for (int jj = 0; jj < 4; jj++) {
            float4 r = *(const float4*)&Rb[(jlane + 4 * jj) * PAD + h];
            float t;
            t = fmaxf(r.x - p0.x, 0.0f); acc[0][jj] = fmaf(t, v.x, acc[0][jj]);
            t = fmaxf(r.y - p0.y, 0.0f); acc[0][jj] = fmaf(t, v.y, acc[0][jj]);
            t = fmaxf(r.z - p0.z, 0.0f); acc[0][jj] = fmaf(t, v.z, acc[0][jj]);
            t = fmaxf(r.w - p0.w, 0.0f); acc[0][jj] = fmaf(t, v.w, acc[0][jj]);
            t = fmaxf(r.x - p1.x, 0.0f); acc[1][jj] = fmaf(t, v.x, acc[1][jj]);
            t = fmaxf(r.y - p1.y, 0.0f); acc[1][jj] = fmaf(t, v.y, acc[1][jj]);
            t = fmaxf(r.z - p1.z, 0.0f); acc[1][jj] = fmaf(t, v.z, acc[1][jj]);
            t = fmaxf(r.w - p1.w, 0.0f); acc[1][jj] = fmaf(t, v.w, acc[1][jj]);
        }
    }

    // write h-quarter partials
#pragma unroll
    for (int ii = 0; ii < 2; ii++)
#pragma unroll
        for (int jj = 0; jj < 4; jj++) {
            int i = ilane + 8 * ii;
            int j = jlane + 4 * jj;
            red[hq * 512 + cl * 256 + i * 16 + j] = acc[ii][jj];
        }
    __syncthreads();

    // epilogue: thread tid handles (c0, c1) for one (i,j)
    {
        int i = tid >> 4;
        int j = tid & 15;
        int o = i * 16 + j;
        float s0 = red[o] + red[512 + o] + red[1024 + o] + red[1536 + o];
        int o2 = o + 256;
        float s1 = red[o2] + red[512 + o2] + red[1024 + o2] + red[1536 + o2];
        int gi = i0 + i, gj = j0 + j;
        float cej0 = g_cumexp[(b * SS + gj) * CC + cbase];
        float cej1 = g_cumexp[(b * SS + gj) * CC + cbase + 1];
        float cei0 = 0.0f, cei1 = 0.0f;
        if (gi > 0) {
            cei0 = g_cumexp[(b * SS + gi - 1) * CC + cbase];
            cei1 = g_cumexp[(b * SS + gi - 1) * CC + cbase + 1];
        }
        float d0 = cej0 - cei0; if (d0 <= 1e-6f) d0 = 100.0f;
        float d1 = cej1 - cei1; if (d1 <= 1e-6f) d1 = 100.0f;
        float2 res;
        res.x = __fdividef(s0, d0) + Vb[cbase];
        res.y = __fdividef(s1, d1) + Vb[cbase + 1];
        *(float2*)&out[((size_t)(b * SS + gi) * SS + gj) * CC + cbase] = res;
    }
}

// ---------------------------------------------------------------------------
extern "C" void kernel_launch(void* const* d_in, const int* in_sizes, int n_in,
                              void* d_out, int out_size)
{
    (void)in_sizes; (void)n_in; (void)out_size;
    const float* memory = (const float*)d_in[0];
    const float* Ww     = (const float*)d_in[1];
    const float* Wb     = (const float*)d_in[2];
    const float* Uw     = (const float*)d_in[3];
    const float* Vw     = (const float*)d_in[4];
    const float* Vb     = (const float*)d_in[5];
    float* out          = (float*)d_out;

    cudaFuncSetAttribute(kernelMain, cudaFuncAttributeMaxDynamicSharedMemorySize,
                         19200 * 4);

    kernelA<<<64, 256>>>(memory, Ww, Wb);
    kernelB1<<<16, 128>>>(Uw);
    kernelB2<<<16, 256>>>(memory);
    kernelMain<<<512, 256, 19200 * 4>>>(Vw, Vb, out);
}

// round 6
// speedup vs baseline: 1.4738x; 1.4738x over previous
#include <cuda_runtime.h>
#include <math.h>

#define BB 2
#define SS 128
#define HH 256
#define CC 8
#define PAD 260        // main-kernel smem row stride (floats, multiple of 4)

// ---------------- scratch (device globals; no allocation allowed) ----------
__device__ float g_z[BB * SS * HH];            // 256 KB
__device__ float g_cumexp[BB * SS * CC];       // 8 KB   [b][s][c]
__device__ float g_cumm[BB * SS * CC * HH];    // 2 MB   [b][s][c][h]

// ---------------------------------------------------------------------------
// Kernel A: z[b,s,h] = relu(memory[b,s,:] . W_w[h,:] + W_b[h])
// grid 128 = (16 s-tiles of 16 rows) x (8 h-tiles of 32); 256 threads.
// Warp covers 4 h; lane = hl*8 + kp (hl = h-local 0..3, kp = k-slice 0..7).
// W reads: 8 kp-lanes cover 128B contiguous per h row -> coalesced (4 segs).
// memory rows staged in smem; LDS per instr = 8 distinct quads x4 broadcast.
// k-reduction via shfl_xor(1,2,4).
// ---------------------------------------------------------------------------
__global__ void __launch_bounds__(256) kernelA(const float* __restrict__ memory,
                                               const float* __restrict__ Ww,
                                               const float* __restrict__ Wb)
{
    __shared__ float Msh[16 * HH];   // 16 KB

    int bid = blockIdx.x;
    int st = bid >> 3;               // s-tile 0..15
    int ht = bid & 7;                // h-tile 0..7
    int s0 = st * 16;                // first global row (b*S+s)
    int tid = threadIdx.x;
    int lane = tid & 31, w = tid >> 5;

    // stage 16 memory rows (coalesced float4)
    for (int t = tid; t < 16 * 64; t += 256) {
        int rr = t >> 6;
        int k4 = t & 63;
        ((float4*)&Msh[rr * HH])[k4] =
            ((const float4*)&memory[(s0 + rr) * HH])[k4];
    }
    __syncthreads();

    int hl = lane >> 3;              // 0..3
    int kp = lane & 7;               // 0..7
    int h = ht * 32 + w * 4 + hl;

    float acc[16];
#pragma unroll
    for (int r = 0; r < 16; r++) acc[r] = 0.0f;

    const float4* wr = (const float4*)&Ww[h * HH];
#pragma unroll
    for (int i = 0; i < 8; i++) {
        float4 wv = wr[i * 8 + kp];          // coalesced across kp
#pragma unroll
        for (int r = 0; r < 16; r++) {
            float4 m = *(const float4*)&Msh[r * HH + i * 32 + kp * 4];
            acc[r] = fmaf(m.x, wv.x,
                     fmaf(m.y, wv.y,
                     fmaf(m.z, wv.z,
                     fmaf(m.w, wv.w, acc[r]))));
        }
    }

    // reduce over kp (lane bits 0..2)
#pragma unroll
    for (int r = 0; r < 16; r++) {
        float v = acc[r];
        v += __shfl_xor_sync(0xffffffffu, v, 1);
        v += __shfl_xor_sync(0xffffffffu, v, 2);
        v += __shfl_xor_sync(0xffffffffu, v, 4);
        acc[r] = v;
    }
    if (kp == 0) {
        float bias = Wb[h];
#pragma unroll
        for (int r = 0; r < 16; r++)
            g_z[(s0 + r) * HH + h] = fmaxf(acc[r] + bias, 0.0f);
    }
}

// ---------------------------------------------------------------------------
// Kernel B (fused B1+B2): per (b,c):
//   score[s] = U_w[c,:].z[b,s,:] (per-thread full dot, high MLP)
//   softmax-exp + inclusive cumsum_s -> g_cumexp; e kept in smem
//   g_cumm[b,s,c,h] = inclusive cumsum_s( memory[b,s,h] * e[s] ), h = tid
// grid 16 = B*C, 256 threads.
// ---------------------------------------------------------------------------
__global__ void __launch_bounds__(256) kernelB(const float* __restrict__ memory,
                                               const float* __restrict__ Uw)
{
    __shared__ float Ush[HH];
    __shared__ float esh[SS];
    __shared__ float wred[4];
    __shared__ float wsum[4];

    int b = blockIdx.x >> 3;
    int c = blockIdx.x & 7;
    int tid = threadIdx.x;
    int lane = tid & 31, w = tid >> 5;

    if (tid < 64)
        ((float4*)Ush)[tid] = ((const float4*)(Uw + c * HH))[tid];
    __syncthreads();

    float sc = 0.0f, e = 0.0f, x = 0.0f;
    if (tid < SS) {
        const float4* zr = (const float4*)&g_z[(b * SS + tid) * HH];
        const float4* u4 = (const float4*)Ush;
#pragma unroll 8
        for (int k = 0; k < 64; k++) {
            float4 z = zr[k];
            float4 u = u4[k];
            sc += z.x * u.x + z.y * u.y + z.z * u.z + z.w * u.w;
        }
        float m = sc;
#pragma unroll
        for (int o = 16; o > 0; o >>= 1)
            m = fmaxf(m, __shfl_xor_sync(0xffffffffu, m, o));
        if (lane == 0) wred[w] = m;
    }
    __syncthreads();
    if (tid < SS) {
        float mx = fmaxf(fmaxf(wred[0], wred[1]), fmaxf(wred[2], wred[3]));
        e = expf(sc - mx);
        x = e;
#pragma unroll
        for (int o = 1; o < 32; o <<= 1) {
            float t = __shfl_up_sync(0xffffffffu, x, o);
            if (lane >= o) x += t;
        }
        if (lane == 31) wsum[w] = x;
    }
    __syncthreads();
    if (tid < SS) {
        float pre = 0.0f;
        for (int ww = 0; ww < w; ww++) pre += wsum[ww];
        esh[tid] = e;
        g_cumexp[(b * SS + tid) * CC + c] = x + pre;
    }
    __syncthreads();

    // phase 3: cumm, h = tid (coalesced loads/stores)
    {
        const float* mp = memory + (size_t)b * SS * HH + tid;
        float* op = g_cumm + ((size_t)b * SS * CC + c) * HH + tid;
        float acc = 0.0f;
#pragma unroll 8
        for (int s = 0; s < SS; s++) {
            acc = fmaf(mp[(size_t)s * HH], esh[s], acc);
            op[(size_t)s * (CC * HH)] = acc;
        }
    }
}

// ---------------------------------------------------------------------------
// Main kernel:
//   out[b,i,j,c] = (sum_h relu(R[j,h]-P[i,h]) * V[c,h]) / denom + V_b[c]
//   P[i,:] = (gi==0 ? 0 : cumm[b,gi-1,c,:]);  R[j,:] = cumm[b,gj,c,:]
// grid 512 = b(2) x i-tile(8) x j-tile(8) x c-pair(4); 256 threads.
// warps: 2 local c x 4 h-quarters; lanes: 8 ilane x 4 jlane; tile 2i x 4j.
// Occupancy 3: reduction buffer aliased into Psh (dead after compute).
// ---------------------------------------------------------------------------
__global__ void __launch_bounds__(256, 3) kernelMain(const float* __restrict__ Vw,
                                                     const float* __restrict__ Vb,
                                                     float* __restrict__ out)
{
    extern __shared__ float sm[];
    float* Psh = sm;                   // 32 * PAD = 8320
    float* Rsh = sm + 8320;            // 8320
    float* Vsh = sm + 16640;           // 512   (total 17152 fl = 68608 B)
    float* red = sm;                   // aliases Psh (2048 fl; P dead by then)

    int bid = blockIdx.x;
    int cpair = bid & 3;
    int jt = (bid >> 2) & 7;
    int it = (bid >> 5) & 7;
    int b = bid >> 8;
    int i0 = it * 16, j0 = jt * 16, cbase = cpair * 2;
    int tid = threadIdx.x;

    // stage V (2 c x 256 h)
    if (tid < 128)
        *(float4*)&Vsh[tid * 4] = *(const float4*)&Vw[cbase * HH + tid * 4];

    // stage P and R tiles: 32 rows each (2c x 16)
    {
        int rr = tid >> 3;             // 0..31
        int c4 = tid & 7;
        int cl = rr >> 4, ir = rr & 15;
        int gi = i0 + ir;
        int gj = j0 + ir;
        const float* srcR = &g_cumm[((size_t)(b * SS + gj) * CC + cbase + cl) * HH];
        const float* srcP = (gi == 0) ? (const float*)0
            : &g_cumm[((size_t)(b * SS + gi - 1) * CC + cbase + cl) * HH];
        float* dstR = &Rsh[rr * PAD];
        float* dstP = &Psh[rr * PAD];
#pragma unroll
        for (int k = 0; k < 8; k++) {
            int h = c4 * 4 + k * 32;
            *(float4*)&dstR[h] = *(const float4*)&srcR[h];
            float4 pv = srcP ? *(const float4*)&srcP[h] : make_float4(0.f, 0.f, 0.f, 0.f);
            *(float4*)&dstP[h] = pv;
        }
    }
    __syncthreads();

    int lane = tid & 31, w = tid >> 5;
    int cl = w & 1;                    // local c
    int hq = w >> 1;                   // h quarter 0..3
    int ilane = lane >> 2;             // 0..7
    int jlane = lane & 3;              // 0..3

    const float* Pb = &Psh[(cl * 16) * PAD];
    const float* Rb = &Rsh[(cl * 16) * PAD];
    const float* Vp = &Vsh[cl * HH];

    float acc[2][4];
#pragma unroll
    for (int ii = 0; ii < 2; ii++)
#pragma unroll
        for (int jj = 0; jj < 4; jj++) acc[ii][jj] = 0.0f;

    int hbase = hq * 64;
#pragma unroll 4
    for (int hh = 0; hh < 64; hh += 4) {
        int h = hbase + hh;
        float4 v  = *(const float4*)&Vp[h];
        float4 p0 = *(const float4*)&Pb[ilane * PAD + h];
        float4 p1 = *(const float4*)&Pb[(ilane + 8) * PAD + h];
#pragma unroll
        for (int jj = 0; jj < 4; jj++) {
            float4 r = *(const float4*)&Rb[(jlane + 4 * jj) * PAD + h];
            float t;
            t = fmaxf(r.x - p0.x, 0.0f); acc[0][jj] = fmaf(t, v.x, acc[0][jj]);
            t = fmaxf(r.y - p0.y, 0.0f); acc[0][jj] = fmaf(t, v.y, acc[0][jj]);
            t = fmaxf(r.z - p0.z, 0.0f); acc[0][jj] = fmaf(t, v.z, acc[0][jj]);
            t = fmaxf(r.w - p0.w, 0.0f); acc[0][jj] = fmaf(t, v.w, acc[0][jj]);
            t = fmaxf(r.x - p1.x, 0.0f); acc[1][jj] = fmaf(t, v.x, acc[1][jj]);
            t = fmaxf(r.y - p1.y, 0.0f); acc[1][jj] = fmaf(t, v.y, acc[1][jj]);
            t = fmaxf(r.z - p1.z, 0.0f); acc[1][jj] = fmaf(t, v.z, acc[1][jj]);
            t = fmaxf(r.w - p1.w, 0.0f); acc[1][jj] = fmaf(t, v.w, acc[1][jj]);
        }
    }

    __syncthreads();   // all warps done reading Psh before red overwrites it

    // write h-quarter partials (red aliases Psh)
#pragma unroll
    for (int ii = 0; ii < 2; ii++)
#pragma unroll
        for (int jj = 0; jj < 4; jj++) {
            int i = ilane + 8 * ii;
            int j = jlane + 4 * jj;
            red[hq * 512 + cl * 256 + i * 16 + j] = acc[ii][jj];
        }
    __syncthreads();

    // epilogue: thread tid handles (c0, c1) for one (i,j)
    {
        int i = tid >> 4;
        int j = tid & 15;
        int o = i * 16 + j;
        float s0 = red[o] + red[512 + o] + red[1024 + o] + red[1536 + o];
        int o2 = o + 256;
        float s1 = red[o2] + red[512 + o2] + red[1024 + o2] + red[1536 + o2];
        int gi = i0 + i, gj = j0 + j;
        float cej0 = g_cumexp[(b * SS + gj) * CC + cbase];
        float cej1 = g_cumexp[(b * SS + gj) * CC + cbase + 1];
        float cei0 = 0.0f, cei1 = 0.0f;
        if (gi > 0) {
            cei0 = g_cumexp[(b * SS + gi - 1) * CC + cbase];
            cei1 = g_cumexp[(b * SS + gi - 1) * CC + cbase + 1];
        }
        float d0 = cej0 - cei0; if (d0 <= 1e-6f) d0 = 100.0f;
        float d1 = cej1 - cei1; if (d1 <= 1e-6f) d1 = 100.0f;
        float2 res;
        res.x = __fdividef(s0, d0) + Vb[cbase];
        res.y = __fdividef(s1, d1) + Vb[cbase + 1];
        *(float2*)&out[((size_t)(b * SS + gi) * SS + gj) * CC + cbase] = res;
    }
}

// ---------------------------------------------------------------------------
extern "C" void kernel_launch(void* const* d_in, const int* in_sizes, int n_in,
                              void* d_out, int out_size)
{
    (void)in_sizes; (void)n_in; (void)out_size;
    const float* memory = (const float*)d_in[0];
    const float* Ww     = (const float*)d_in[1];
    const float* Wb     = (const float*)d_in[2];
    const float* Uw     = (const float*)d_in[3];
    const float* Vw     = (const float*)d_in[4];
    const float* Vb     = (const float*)d_in[5];
    float* out          = (float*)d_out;

    cudaFuncSetAttribute(kernelMain, cudaFuncAttributeMaxDynamicSharedMemorySize,
                         17152 * 4);

    kernelA<<<128, 256>>>(memory, Ww, Wb);
    kernelB<<<16, 256>>>(memory, Uw);
    kernelMain<<<512, 256, 17152 * 4>>>(Vw, Vb, out);
}

// round 7
// speedup vs baseline: 1.5643x; 1.0614x over previous
#include <cuda_runtime.h>
#include <math.h>

#define BB 2
#define SS 128
#define HH 256
#define CC 8
#define PAD 260        // main-kernel smem row stride (floats, multiple of 4)

// ---------------- scratch (device globals; no allocation allowed) ----------
__device__ float g_z[BB * SS * HH];            // 256 KB
__device__ float g_e[BB * CC * SS];            // 8 KB   [b][c][s]
__device__ float g_cumexp[BB * SS * CC];       // 8 KB   [b][s][c]
__device__ float g_cumm[BB * SS * CC * HH];    // 2 MB   [b][s][c][h]

// ---------------------------------------------------------------------------
// Kernel A: z[b,s,h] = relu(memory[b,s,:] . W_w[h,:] + W_b[h])
// grid 512 = (64 s-tiles of 4 rows) x (8 h-tiles of 32); 256 threads.
// Warp covers 4 h; lane = hl*8 + kp. W reads coalesced (4x128B per warp).
// 4KB smem, low regs -> 3-4 CTAs/SM for latency hiding (fixes occ=12%).
// ---------------------------------------------------------------------------
__global__ void __launch_bounds__(256) kernelA(const float* __restrict__ memory,
                                               const float* __restrict__ Ww,
                                               const float* __restrict__ Wb)
{
    __shared__ float Msh[4 * HH];    // 4 KB

    int bid = blockIdx.x;
    int st = bid >> 3;               // s-tile 0..63
    int ht = bid & 7;                // h-tile 0..7
    int s0 = st * 4;                 // first global row (b*S+s)
    int tid = threadIdx.x;
    int lane = tid & 31, w = tid >> 5;

    // stage 4 memory rows (256 float4, one per thread)
    {
        int rr = tid >> 6;
        int k4 = tid & 63;
        ((float4*)&Msh[rr * HH])[k4] =
            ((const float4*)&memory[(s0 + rr) * HH])[k4];
    }
    __syncthreads();

    int hl = lane >> 3;              // 0..3
    int kp = lane & 7;               // 0..7
    int h = ht * 32 + w * 4 + hl;

    float acc[4] = {0.0f, 0.0f, 0.0f, 0.0f};

    const float4* wr = (const float4*)&Ww[h * HH];
#pragma unroll
    for (int i = 0; i < 8; i++) {
        float4 wv = wr[i * 8 + kp];          // coalesced across kp
#pragma unroll
        for (int r = 0; r < 4; r++) {
            float4 m = *(const float4*)&Msh[r * HH + i * 32 + kp * 4];
            acc[r] = fmaf(m.x, wv.x,
                     fmaf(m.y, wv.y,
                     fmaf(m.z, wv.z,
                     fmaf(m.w, wv.w, acc[r]))));
        }
    }

    // reduce over kp (lane bits 0..2)
#pragma unroll
    for (int r = 0; r < 4; r++) {
        float v = acc[r];
        v += __shfl_xor_sync(0xffffffffu, v, 1);
        v += __shfl_xor_sync(0xffffffffu, v, 2);
        v += __shfl_xor_sync(0xffffffffu, v, 4);
        acc[r] = v;
    }
    if (kp == 0) {
        float bias = Wb[h];
#pragma unroll
        for (int r = 0; r < 4; r++)
            g_z[(s0 + r) * HH + h] = fmaxf(acc[r] + bias, 0.0f);
    }
}

// ---------------------------------------------------------------------------
// Kernel B1: per (b,c): score[s] = U_w[c,:].z[b,s,:]; softmax-exp; inclusive
// cumsum over s -> g_cumexp; e -> g_e. grid 16 = B*C, 128 threads.
// ---------------------------------------------------------------------------
__global__ void __launch_bounds__(128) kernelB1(const float* __restrict__ Uw)
{
    __shared__ float Ush[HH];
    __shared__ float wred[4];
    __shared__ float wsum[4];

    int b = blockIdx.x >> 3;
    int c = blockIdx.x & 7;
    int tid = threadIdx.x;
    int lane = tid & 31, w = tid >> 5;

    if (tid < 64)
        ((float4*)Ush)[tid] = ((const float4*)(Uw + c * HH))[tid];
    __syncthreads();

    // per-thread full dot (64 independent float4 loads -> high MLP)
    float sc = 0.0f;
    {
        const float4* zr = (const float4*)&g_z[(b * SS + tid) * HH];
        const float4* u4 = (const float4*)Ush;
#pragma unroll 8
        for (int k = 0; k < 64; k++) {
            float4 z = zr[k];
            float4 u = u4[k];
            sc += z.x * u.x + z.y * u.y + z.z * u.z + z.w * u.w;
        }
    }
    float m = sc;
#pragma unroll
    for (int o = 16; o > 0; o >>= 1)
        m = fmaxf(m, __shfl_xor_sync(0xffffffffu, m, o));
    if (lane == 0) wred[w] = m;
    __syncthreads();
    float mx = fmaxf(fmaxf(wred[0], wred[1]), fmaxf(wred[2], wred[3]));

    float e = expf(sc - mx);
    float x = e;
#pragma unroll
    for (int o = 1; o < 32; o <<= 1) {
        float t = __shfl_up_sync(0xffffffffu, x, o);
        if (lane >= o) x += t;
    }
    if (lane == 31) wsum[w] = x;
    __syncthreads();
    float pre = 0.0f;
    for (int ww = 0; ww < w; ww++) pre += wsum[ww];

    g_e[(b * CC + c) * SS + tid] = e;
    g_cumexp[(b * SS + tid) * CC + c] = x + pre;
}

// ---------------------------------------------------------------------------
// Kernel B2: g_cumm[b,s,c,h] = inclusive cumsum_s( memory[b,s,h] * e[b,c,s] )
// grid 128 = (b,c) x 8 h-chunks of 32; 256 threads = 32 h-lanes x 8 s-groups
// of 16. Two-pass: per-thread running sum over 16 s, smem prefix over groups.
// All LDG/STG 128B coalesced per warp.
// ---------------------------------------------------------------------------
__global__ void __launch_bounds__(256) kernelB2(const float* __restrict__ memory)
{
    __shared__ float esh[SS];
    __shared__ float psum[8][32];

    int bid = blockIdx.x;
    int hc = bid & 7;
    int bc = bid >> 3;               // b*CC + c
    int b = bc >> 3;
    int c = bc & 7;
    int tid = threadIdx.x;
    int hl = tid & 31;
    int sg = tid >> 5;               // s-group 0..7

    if (tid < SS) esh[tid] = g_e[bc * SS + tid];
    __syncthreads();

    int h = hc * 32 + hl;
    const float* mp = memory + (size_t)b * SS * HH + h;

    float val[16];
    float run = 0.0f;
#pragma unroll
    for (int k = 0; k < 16; k++) {
        int s = sg * 16 + k;
        run = fmaf(mp[(size_t)s * HH], esh[s], run);
        val[k] = run;
    }
    psum[sg][hl] = run;
    __syncthreads();

    float off = 0.0f;
    for (int t = 0; t < sg; t++) off += psum[t][hl];

    float* op = g_cumm + ((size_t)b * SS * CC + c) * HH + h;
#pragma unroll
    for (int k = 0; k < 16; k++) {
        int s = sg * 16 + k;
        op[(size_t)s * (CC * HH)] = val[k] + off;
    }
}

// ---------------------------------------------------------------------------
// Main kernel:
//   out[b,i,j,c] = (sum_h relu(R[j,h]-P[i,h]) * V[c,h]) / denom + V_b[c]
// grid 512 = b(2) x i-tile(8) x j-tile(8) x c-pair(4); 256 threads.
// warps: 2 local c x 4 h-quarters; lanes: 8 ilane x 4 jlane; tile 2i x 4j.
// Occupancy 3: reduction buffer aliased into Psh (dead after compute).
// ---------------------------------------------------------------------------
__global__ void __launch_bounds__(256, 3) kernelMain(const float* __restrict__ Vw,
                                                     const float* __restrict__ Vb,
                                                     float* __restrict__ out)
{
    extern __shared__ float sm[];
    float* Psh = sm;                   // 32 * PAD = 8320
    float* Rsh = sm + 8320;            // 8320
    float* Vsh = sm + 16640;           // 512   (total 17152 fl = 68608 B)
    float* red = sm;                   // aliases Psh (2048 fl; P dead by then)

    int bid = blockIdx.x;
    int cpair = bid & 3;
    int jt = (bid >> 2) & 7;
    int it = (bid >> 5) & 7;
    int b = bid >> 8;
    int i0 = it * 16, j0 = jt * 16, cbase = cpair * 2;
    int tid = threadIdx.x;

    // stage V (2 c x 256 h)
    if (tid < 128)
        *(float4*)&Vsh[tid * 4] = *(const float4*)&Vw[cbase * HH + tid * 4];

    // stage P and R tiles: 32 rows each (2c x 16)
    {
        int rr = tid >> 3;             // 0..31
        int c4 = tid & 7;
        int cl = rr >> 4, ir = rr & 15;
        int gi = i0 + ir;
        int gj = j0 + ir;
        const float* srcR = &g_cumm[((size_t)(b * SS + gj) * CC + cbase + cl) * HH];
        const float* srcP = (gi == 0) ? (const float*)0
            : &g_cumm[((size_t)(b * SS + gi - 1) * CC + cbase + cl) * HH];
        float* dstR = &Rsh[rr * PAD];
        float* dstP = &Psh[rr * PAD];
#pragma unroll
        for (int k = 0; k < 8; k++) {
            int h = c4 * 4 + k * 32;
            *(float4*)&dstR[h] = *(const float4*)&srcR[h];
            float4 pv = srcP ? *(const float4*)&srcP[h] : make_float4(0.f, 0.f, 0.f, 0.f);
            *(float4*)&dstP[h] = pv;
        }
    }
    __syncthreads();

    int lane = tid & 31, w = tid >> 5;
    int cl = w & 1;                    // local c
    int hq = w >> 1;                   // h quarter 0..3
    int ilane = lane >> 2;             // 0..7
    int jlane = lane & 3;              // 0..3

    const float* Pb = &Psh[(cl * 16) * PAD];
    const float* Rb = &Rsh[(cl * 16) * PAD];
    const float* Vp = &Vsh[cl * HH];

    float acc[2][4];
#pragma unroll
    for (int ii = 0; ii < 2; ii++)
#pragma unroll
        for (int jj = 0; jj < 4; jj++) acc[ii][jj] = 0.0f;

    int hbase = hq * 64;
#pragma unroll 4
    for (int hh = 0; hh < 64; hh += 4) {
        int h = hbase + hh;
        float4 v  = *(const float4*)&Vp[h];
        float4 p0 = *(const float4*)&Pb[ilane * PAD + h];
        float4 p1 = *(const float4*)&Pb[(ilane + 8) * PAD + h];
#pragma unroll
        for (int jj = 0; jj < 4; jj++) {
            float4 r = *(const float4*)&Rb[(jlane + 4 * jj) * PAD + h];
            float t;
            t = fmaxf(r.x - p0.x, 0.0f); acc[0][jj] = fmaf(t, v.x, acc[0][jj]);
            t = fmaxf(r.y - p0.y, 0.0f); acc[0][jj] = fmaf(t, v.y, acc[0][jj]);
            t = fmaxf(r.z - p0.z, 0.0f); acc[0][jj] = fmaf(t, v.z, acc[0][jj]);
            t = fmaxf(r.w - p0.w, 0.0f); acc[0][jj] = fmaf(t, v.w, acc[0][jj]);
            t = fmaxf(r.x - p1.x, 0.0f); acc[1][jj] = fmaf(t, v.x, acc[1][jj]);
            t = fmaxf(r.y - p1.y, 0.0f); acc[1][jj] = fmaf(t, v.y, acc[1][jj]);
            t = fmaxf(r.z - p1.z, 0.0f); acc[1][jj] = fmaf(t, v.z, acc[1][jj]);
            t = fmaxf(r.w - p1.w, 0.0f); acc[1][jj] = fmaf(t, v.w, acc[1][jj]);
        }
    }

    __syncthreads();   // all warps done reading Psh before red overwrites it

    // write h-quarter partials (red aliases Psh)
#pragma unroll
    for (int ii = 0; ii < 2; ii++)
#pragma unroll
        for (int jj = 0; jj < 4; jj++) {
            int i = ilane + 8 * ii;
            int j = jlane + 4 * jj;
            red[hq * 512 + cl * 256 + i * 16 + j] = acc[ii][jj];
        }
    __syncthreads();

    // epilogue: thread tid handles (c0, c1) for one (i,j)
    {
        int i = tid >> 4;
        int j = tid & 15;
        int o = i * 16 + j;
        float s0 = red[o] + red[512 + o] + red[1024 + o] + red[1536 + o];
        int o2 = o + 256;
        float s1 = red[o2] + red[512 + o2] + red[1024 + o2] + red[1536 + o2];
        int gi = i0 + i, gj = j0 + j;
        float cej0 = g_cumexp[(b * SS + gj) * CC + cbase];
        float cej1 = g_cumexp[(b * SS + gj) * CC + cbase + 1];
        float cei0 = 0.0f, cei1 = 0.0f;
        if (gi > 0) {
            cei0 = g_cumexp[(b * SS + gi - 1) * CC + cbase];
            cei1 = g_cumexp[(b * SS + gi - 1) * CC + cbase + 1];
        }
        float d0 = cej0 - cei0; if (d0 <= 1e-6f) d0 = 100.0f;
        float d1 = cej1 - cei1; if (d1 <= 1e-6f) d1 = 100.0f;
        float2 res;
        res.x = __fdividef(s0, d0) + Vb[cbase];
        res.y = __fdividef(s1, d1) + Vb[cbase + 1];
        *(float2*)&out[((size_t)(b * SS + gi) * SS + gj) * CC + cbase] = res;
    }
}

// ---------------------------------------------------------------------------
extern "C" void kernel_launch(void* const* d_in, const int* in_sizes, int n_in,
                              void* d_out, int out_size)
{
    (void)in_sizes; (void)n_in; (void)out_size;
    const float* memory = (const float*)d_in[0];
    const float* Ww     = (const float*)d_in[1];
    const float* Wb     = (const float*)d_in[2];
    const float* Uw     = (const float*)d_in[3];
    const float* Vw     = (const float*)d_in[4];
    const float* Vb     = (const float*)d_in[5];
    float* out          = (float*)d_out;

    cudaFuncSetAttribute(kernelMain, cudaFuncAttributeMaxDynamicSharedMemorySize,
                         17152 * 4);

    kernelA<<<512, 256>>>(memory, Ww, Wb);
    kernelB1<<<16, 128>>>(Uw);
    kernelB2<<<128, 256>>>(memory);
    kernelMain<<<512, 256, 17152 * 4>>>(Vw, Vb, out);
}